// round 11
// baseline (speedup 1.0000x reference)
#include <cuda_runtime.h>

__device__ __forceinline__ float ex2_fast(float x) {
    float y;
    asm("ex2.approx.ftz.f32 %0, %1;" : "=f"(y) : "f"(x));
    return y;
}
__device__ __forceinline__ float rcp_fast(float x) {
    float y;
    asm("rcp.approx.ftz.f32 %0, %1;" : "=f"(y) : "f"(x));
    return y;
}
__device__ __forceinline__ float cos_fast(float x) {
    float y;
    asm("cos.approx.ftz.f32 %0, %1;" : "=f"(y) : "f"(x));
    return y;
}

#define N_LAYERS 5
#define Q_DEPTH  2

// smem constant layout:
// [0..19]  W''[l][4]  (scale-folded AND pre-multiplied by -2*log2(e))
// [20..29] b''[l][2]  (same folding)
// [30] wf0'  [31] wf1'  [32] bf' + K0
// [33] K1  [34] K2  [35] K3-K4  [36] K4
#define NCOEF 37

__device__ __forceinline__ void build_coefs(
    float* sc,
    const float* __restrict__ Ws, const float* __restrict__ bs,
    const float* __restrict__ scales, const float* __restrict__ shifts,
    const float* __restrict__ Wf, const float* __restrict__ bf,
    const float* __restrict__ theta)
{
    const float CEXP = -2.8853900817779268f;   // -2*log2(e): t = 2^(CEXP*z) = e^(-2z)

    // ---- fold scale/shift of layer l-1 into layer l, then scale by CEXP ----
    sc[0] = CEXP * Ws[0]; sc[1] = CEXP * Ws[1];
    sc[2] = CEXP * Ws[2]; sc[3] = CEXP * Ws[3];
    sc[20] = CEXP * bs[0]; sc[21] = CEXP * bs[1];
#pragma unroll
    for (int l = 1; l < N_LAYERS; ++l) {
        float sc0 = scales[(l-1)*2+0], sc1 = scales[(l-1)*2+1];
        float sh0 = shifts[(l-1)*2+0], sh1 = shifts[(l-1)*2+1];
        float w00 = Ws[l*4+0], w01 = Ws[l*4+1], w10 = Ws[l*4+2], w11 = Ws[l*4+3];
        sc[l*4+0] = CEXP * w00 * sc0;
        sc[l*4+1] = CEXP * w01 * sc1;
        sc[l*4+2] = CEXP * w10 * sc0;
        sc[l*4+3] = CEXP * w11 * sc1;
        sc[20+l*2+0] = CEXP * fmaf(w00, sh0, fmaf(w01, sh1, bs[l*2+0]));
        sc[20+l*2+1] = CEXP * fmaf(w10, sh0, fmaf(w11, sh1, bs[l*2+1]));
    }
    float lsc0 = scales[(N_LAYERS-1)*2+0], lsc1 = scales[(N_LAYERS-1)*2+1];
    float lsh0 = shifts[(N_LAYERS-1)*2+0], lsh1 = shifts[(N_LAYERS-1)*2+1];
    sc[30] = Wf[0] * lsc0;
    sc[31] = Wf[1] * lsc1;
    float bfp = fmaf(Wf[0], lsh0, fmaf(Wf[1], lsh1, bf[0]));

    // ---- U = prod_d [ CZ * (RY1 (x) RY0) ], real 4x4; need rows 0 and 3 ----
    float U[4][4];
#pragma unroll
    for (int i = 0; i < 4; ++i)
#pragma unroll
        for (int j = 0; j < 4; ++j)
            U[i][j] = (i == j) ? 1.0f : 0.0f;

#pragma unroll
    for (int d = 0; d < Q_DEPTH; ++d) {
        float a0 = theta[d*2+0] * 0.5f;
        float a1 = theta[d*2+1] * 0.5f;
        float s0, c0, s1, c1;
        __sincosf(a0, &s0, &c0);
        __sincosf(a1, &s1, &c1);
        float ry0[2][2] = {{c0, -s0}, {s0, c0}};
        float ry1[2][2] = {{c1, -s1}, {s1, c1}};
        float M[4][4];
#pragma unroll
        for (int i = 0; i < 4; ++i)
#pragma unroll
            for (int j = 0; j < 4; ++j) {
                float acc = 0.0f;
#pragma unroll
                for (int k = 0; k < 4; ++k)
                    acc = fmaf(ry1[i>>1][k>>1] * ry0[i&1][k&1], U[k][j], acc);
                M[i][j] = acc;
            }
#pragma unroll
        for (int i = 0; i < 4; ++i)
#pragma unroll
            for (int j = 0; j < 4; ++j)
                U[i][j] = (i == 3) ? -M[i][j] : M[i][j];   // CZ flips |11> row
    }

    // q = K0 + K1 cos x0 + K2 cos x1 + K3 cos x0 cos x1 + K4 sin x0 sin x1
    float a = U[0][0]*U[0][0], b = U[0][1]*U[0][1], c = U[0][2]*U[0][2], dd = U[0][3]*U[0][3];
    float e = U[3][0]*U[3][0], f = U[3][1]*U[3][1], g = U[3][2]*U[3][2], h = U[3][3]*U[3][3];
    float cross0 = 2.0f * (U[0][1]*U[0][2] - U[0][0]*U[0][3]);
    float cross3 = 2.0f * (U[3][1]*U[3][2] - U[3][0]*U[3][3]);
    float K0 = 0.5f * ((a + b + c + dd) - (e + f + g + h));
    float K1 = 0.5f * ((a - b + c - dd) - (e - f + g - h));
    float K2 = 0.5f * ((a + b - c - dd) - (e + f - g - h));
    float K3 = 0.5f * ((a - b - c + dd) - (e - f - g + h));
    float K4 = 0.5f * (cross0 - cross3);
    sc[32] = bfp + K0;
    sc[33] = K1;
    sc[34] = K2;
    sc[35] = K3 - K4;     // coefficient of C0*C1 after product-to-sum
    sc[36] = K4;          // coefficient of cos(x0 - x1)
}

__global__ __launch_bounds__(256, 3)
void fraud_hybrid_fused(
    const float4* __restrict__ x4,    // [N/2] of (x0,x1) pairs
    float4*       __restrict__ out4,  // [N/4]
    const float*  __restrict__ x_raw,
    float*        __restrict__ out_raw,
    const float*  __restrict__ Ws, const float* __restrict__ bs,
    const float*  __restrict__ scales, const float* __restrict__ shifts,
    const float*  __restrict__ Wf, const float* __restrict__ bf,
    const float*  __restrict__ theta,
    int n, int noct)
{
    __shared__ float sc[NCOEF + 3];
    if (threadIdx.x == 0)
        build_coefs(sc, Ws, bs, scales, shifts, Wf, bf, theta);
    __syncthreads();

    float w[N_LAYERS][4], bz[N_LAYERS][2];
#pragma unroll
    for (int l = 0; l < N_LAYERS; ++l) {
        w[l][0] = sc[l*4+0]; w[l][1] = sc[l*4+1];
        w[l][2] = sc[l*4+2]; w[l][3] = sc[l*4+3];
        bz[l][0] = sc[20+l*2+0]; bz[l][1] = sc[20+l*2+1];
    }
    const float wf0 = sc[30], wf1 = sc[31], bfK = sc[32];
    const float K1 = sc[33], K2 = sc[34], K34 = sc[35], K4 = sc[36];

    // quantum head: 3 cos (MUFU@8) + 5 FMA
    auto qhead = [&](float x0, float x1) -> float {
        float C0 = cos_fast(x0);
        float C1 = cos_fast(x1);
        float CD = cos_fast(x0 - x1);       // sin x0 sin x1 = CD - C0*C1
        float cc = C0 * C1;
        return fmaf(K1, C0, fmaf(K2, C1, fmaf(K34, cc, K4 * CD)));
    };

    // backbone: tanh pair via shared-rcp exp identity.
    // z'' already includes the -2*log2(e) factor (folded into weights), so
    // t = ex2(z'') = e^{-2z};  tanh(z) = (1-t)/(1+t).
    // One rcp serves both channels: R = 1/((1+t0)(1+t1)).
    // Clamp z'' <= 28.8 (z >= -9.98): prevents ex2 overflow; tanh(-9.98) = -1
    // to within 4e-9 anyway. Underflow side (t -> 0, tanh -> 1) is exact.
    auto backbone = [&](float x0, float x1) -> float {
        float h0 = x0, h1 = x1;
#pragma unroll
        for (int l = 0; l < N_LAYERS; ++l) {
            float z0 = fmaf(w[l][0], h0, fmaf(w[l][1], h1, bz[l][0]));
            float z1 = fmaf(w[l][2], h0, fmaf(w[l][3], h1, bz[l][1]));
            z0 = fminf(z0, 28.8f);
            z1 = fminf(z1, 28.8f);
            float t0 = ex2_fast(z0);
            float t1 = ex2_fast(z1);
            float A = 1.0f + t0;
            float B = 1.0f + t1;
            float R = rcp_fast(A * B);
            h0 = ((1.0f - t0) * B) * R;
            h1 = ((1.0f - t1) * A) * R;
        }
        return fmaf(wf0, h0, fmaf(wf1, h1, bfK));
    };

    const int tid = blockIdx.x * blockDim.x + threadIdx.x;

    if (tid < noct) {
        const int i = tid;
        float4 a = __ldg(&x4[4*i+0]);
        float4 b = __ldg(&x4[4*i+1]);
        float4 c = __ldg(&x4[4*i+2]);
        float4 d = __ldg(&x4[4*i+3]);

        float q0 = qhead(a.x, a.y), q1 = qhead(a.z, a.w);
        float q2 = qhead(b.x, b.y), q3 = qhead(b.z, b.w);
        float q4 = qhead(c.x, c.y), q5 = qhead(c.z, c.w);
        float q6 = qhead(d.x, d.y), q7 = qhead(d.z, d.w);

        float r0 = backbone(a.x, a.y) + q0;
        float r1 = backbone(a.z, a.w) + q1;
        float r2 = backbone(b.x, b.y) + q2;
        float r3 = backbone(b.z, b.w) + q3;
        float r4 = backbone(c.x, c.y) + q4;
        float r5 = backbone(c.z, c.w) + q5;
        float r6 = backbone(d.x, d.y) + q6;
        float r7 = backbone(d.z, d.w) + q7;

        out4[2*i+0] = make_float4(r0, r1, r2, r3);
        out4[2*i+1] = make_float4(r4, r5, r6, r7);
    }

    // tail (n not multiple of 8) — defensive; N = 4M is divisible
    int base = noct * 8;
    int rem = n - base;
    if (tid < rem) {
        int idx = base + tid;
        float x0 = x_raw[2*idx], x1 = x_raw[2*idx+1];
        out_raw[idx] = backbone(x0, x1) + qhead(x0, x1);
    }
}

extern "C" void kernel_launch(void* const* d_in, const int* in_sizes, int n_in,
                              void* d_out, int out_size) {
    const float* x      = (const float*)d_in[0];  // [N,2]
    const float* Ws     = (const float*)d_in[1];  // [5,2,2]
    const float* bs     = (const float*)d_in[2];  // [5,2]
    const float* scales = (const float*)d_in[3];  // [5,2]
    const float* shifts = (const float*)d_in[4];  // [5,2]
    const float* Wf     = (const float*)d_in[5];  // [1,2]
    const float* bf     = (const float*)d_in[6];  // [1]
    const float* theta  = (const float*)d_in[7];  // [2,2]

    const int n = out_size;
    const int noct = n >> 3;              // 8 elements per thread, one pass

    const int threads = 256;
    int blocks = (noct + threads - 1) / threads;   // exact: 2048 at N=4M
    if (blocks < 1) blocks = 1;

    fraud_hybrid_fused<<<blocks, threads>>>(
        (const float4*)x, (float4*)d_out, x, (float*)d_out,
        Ws, bs, scales, shifts, Wf, bf, theta, n, noct);
}

// round 13
// speedup vs baseline: 1.2995x; 1.2995x over previous
#include <cuda_runtime.h>
#include <cuda_fp16.h>
#include <cstdint>

__device__ __forceinline__ float cos_fast(float x) {
    float y;
    asm("cos.approx.ftz.f32 %0, %1;" : "=f"(y) : "f"(x));
    return y;
}
// One MUFU instruction -> two tanhs (sm_75+)
__device__ __forceinline__ __half2 tanh_h2(__half2 x) {
    __half2 y;
    asm("tanh.approx.f16x2 %0, %1;"
        : "=r"(*reinterpret_cast<uint32_t*>(&y))
        : "r"(*reinterpret_cast<const uint32_t*>(&x)));
    return y;
}

#define N_LAYERS 5
#define Q_DEPTH  2

// smem constant layout:
// [0..19]  W'[l][4]   (scale-folded; layer 0 original)
// [20..29] b'[l][2]
// [30] wf0'  [31] wf1'  [32] bf' + K0
// [33] K1  [34] K2  [35] K3-K4  [36] K4
#define NCOEF 37

__device__ __forceinline__ void build_coefs(
    float* sc,
    const float* __restrict__ Ws, const float* __restrict__ bs,
    const float* __restrict__ scales, const float* __restrict__ shifts,
    const float* __restrict__ Wf, const float* __restrict__ bf,
    const float* __restrict__ theta)
{
    // ---- fold scale/shift of layer l-1 into layer l ----
    sc[0] = Ws[0]; sc[1] = Ws[1]; sc[2] = Ws[2]; sc[3] = Ws[3];
    sc[20] = bs[0]; sc[21] = bs[1];
#pragma unroll
    for (int l = 1; l < N_LAYERS; ++l) {
        float sc0 = scales[(l-1)*2+0], sc1 = scales[(l-1)*2+1];
        float sh0 = shifts[(l-1)*2+0], sh1 = shifts[(l-1)*2+1];
        float w00 = Ws[l*4+0], w01 = Ws[l*4+1], w10 = Ws[l*4+2], w11 = Ws[l*4+3];
        sc[l*4+0] = w00 * sc0;
        sc[l*4+1] = w01 * sc1;
        sc[l*4+2] = w10 * sc0;
        sc[l*4+3] = w11 * sc1;
        sc[20+l*2+0] = fmaf(w00, sh0, fmaf(w01, sh1, bs[l*2+0]));
        sc[20+l*2+1] = fmaf(w10, sh0, fmaf(w11, sh1, bs[l*2+1]));
    }
    float lsc0 = scales[(N_LAYERS-1)*2+0], lsc1 = scales[(N_LAYERS-1)*2+1];
    float lsh0 = shifts[(N_LAYERS-1)*2+0], lsh1 = shifts[(N_LAYERS-1)*2+1];
    sc[30] = Wf[0] * lsc0;
    sc[31] = Wf[1] * lsc1;
    float bfp = fmaf(Wf[0], lsh0, fmaf(Wf[1], lsh1, bf[0]));

    // ---- U = prod_d [ CZ * (RY1 (x) RY0) ], real 4x4; rows 0 and 3 ----
    float U[4][4];
#pragma unroll
    for (int i = 0; i < 4; ++i)
#pragma unroll
        for (int j = 0; j < 4; ++j)
            U[i][j] = (i == j) ? 1.0f : 0.0f;

#pragma unroll
    for (int d = 0; d < Q_DEPTH; ++d) {
        float a0 = theta[d*2+0] * 0.5f;
        float a1 = theta[d*2+1] * 0.5f;
        float s0, c0, s1, c1;
        __sincosf(a0, &s0, &c0);
        __sincosf(a1, &s1, &c1);
        float ry0[2][2] = {{c0, -s0}, {s0, c0}};
        float ry1[2][2] = {{c1, -s1}, {s1, c1}};
        float M[4][4];
#pragma unroll
        for (int i = 0; i < 4; ++i)
#pragma unroll
            for (int j = 0; j < 4; ++j) {
                float acc = 0.0f;
#pragma unroll
                for (int k = 0; k < 4; ++k)
                    acc = fmaf(ry1[i>>1][k>>1] * ry0[i&1][k&1], U[k][j], acc);
                M[i][j] = acc;
            }
#pragma unroll
        for (int i = 0; i < 4; ++i)
#pragma unroll
            for (int j = 0; j < 4; ++j)
                U[i][j] = (i == 3) ? -M[i][j] : M[i][j];   // CZ flips |11> row
    }

    // q = K0 + K1 cos x0 + K2 cos x1 + K3 cos x0 cos x1 + K4 sin x0 sin x1
    float a = U[0][0]*U[0][0], b = U[0][1]*U[0][1], c = U[0][2]*U[0][2], dd = U[0][3]*U[0][3];
    float e = U[3][0]*U[3][0], f = U[3][1]*U[3][1], g = U[3][2]*U[3][2], h = U[3][3]*U[3][3];
    float cross0 = 2.0f * (U[0][1]*U[0][2] - U[0][0]*U[0][3]);
    float cross3 = 2.0f * (U[3][1]*U[3][2] - U[3][0]*U[3][3]);
    float K0 = 0.5f * ((a + b + c + dd) - (e + f + g + h));
    float K1 = 0.5f * ((a - b + c - dd) - (e - f + g - h));
    float K2 = 0.5f * ((a + b - c - dd) - (e + f - g - h));
    float K3 = 0.5f * ((a - b - c + dd) - (e - f - g + h));
    float K4 = 0.5f * (cross0 - cross3);
    sc[32] = bfp + K0;
    sc[33] = K1;
    sc[34] = K2;
    sc[35] = K3 - K4;     // coefficient of C0*C1 after product-to-sum
    sc[36] = K4;          // coefficient of cos(x0 - x1)
}

__global__ __launch_bounds__(256, 3)
void fraud_hybrid_fused(
    const float4* __restrict__ x4,    // [N/2] of (x0,x1) pairs
    float4*       __restrict__ out4,  // [N/4]
    const float*  __restrict__ x_raw,
    float*        __restrict__ out_raw,
    const float*  __restrict__ Ws, const float* __restrict__ bs,
    const float*  __restrict__ scales, const float* __restrict__ shifts,
    const float*  __restrict__ Wf, const float* __restrict__ bf,
    const float*  __restrict__ theta,
    int n, int noct)
{
    __shared__ float sc[NCOEF + 3];
    if (threadIdx.x == 0)
        build_coefs(sc, Ws, bs, scales, shifts, Wf, bf, theta);
    __syncthreads();

    float w[N_LAYERS][4], bz[N_LAYERS][2];
#pragma unroll
    for (int l = 0; l < N_LAYERS; ++l) {
        w[l][0] = sc[l*4+0]; w[l][1] = sc[l*4+1];
        w[l][2] = sc[l*4+2]; w[l][3] = sc[l*4+3];
        bz[l][0] = sc[20+l*2+0]; bz[l][1] = sc[20+l*2+1];
    }
    const float wf0 = sc[30], wf1 = sc[31], bfK = sc[32];
    const float K1 = sc[33], K2 = sc[34], K34 = sc[35], K4 = sc[36];

    // quantum head: 3 cos (MUFU@8) + 5 FMA, all fp32
    auto qhead = [&](float x0, float x1) -> float {
        float C0 = cos_fast(x0);
        float C1 = cos_fast(x1);
        float CD = cos_fast(x0 - x1);       // sin x0 sin x1 = CD - C0*C1
        float cc = C0 * C1;
        return fmaf(K1, C0, fmaf(K2, C1, fmaf(K34, cc, K4 * CD)));
    };

    // backbone: fp32 linear algebra, paired tanh via ONE tanh.approx.f16x2
    // per layer (halves the heavy-MUFU cycle count vs 2x tanh.approx.f32).
    auto backbone = [&](float x0, float x1) -> float {
        float h0 = x0, h1 = x1;
#pragma unroll
        for (int l = 0; l < N_LAYERS; ++l) {
            float z0 = fmaf(w[l][0], h0, fmaf(w[l][1], h1, bz[l][0]));
            float z1 = fmaf(w[l][2], h0, fmaf(w[l][3], h1, bz[l][1]));
            __half2 zh = __floats2half2_rn(z0, z1);
            __half2 th = tanh_h2(zh);
            float2 t = __half22float2(th);
            h0 = t.x;
            h1 = t.y;
        }
        return fmaf(wf0, h0, fmaf(wf1, h1, bfK));
    };

    const int tid = blockIdx.x * blockDim.x + threadIdx.x;

    if (tid < noct) {
        const int i = tid;
        float4 a = __ldg(&x4[4*i+0]);
        float4 b = __ldg(&x4[4*i+1]);
        float4 c = __ldg(&x4[4*i+2]);
        float4 d = __ldg(&x4[4*i+3]);

        float q0 = qhead(a.x, a.y), q1 = qhead(a.z, a.w);
        float q2 = qhead(b.x, b.y), q3 = qhead(b.z, b.w);
        float q4 = qhead(c.x, c.y), q5 = qhead(c.z, c.w);
        float q6 = qhead(d.x, d.y), q7 = qhead(d.z, d.w);

        float r0 = backbone(a.x, a.y) + q0;
        float r1 = backbone(a.z, a.w) + q1;
        float r2 = backbone(b.x, b.y) + q2;
        float r3 = backbone(b.z, b.w) + q3;
        float r4 = backbone(c.x, c.y) + q4;
        float r5 = backbone(c.z, c.w) + q5;
        float r6 = backbone(d.x, d.y) + q6;
        float r7 = backbone(d.z, d.w) + q7;

        out4[2*i+0] = make_float4(r0, r1, r2, r3);
        out4[2*i+1] = make_float4(r4, r5, r6, r7);
    }

    // tail (n not multiple of 8) — defensive; N = 4M is divisible
    int base = noct * 8;
    int rem = n - base;
    if (tid < rem) {
        int idx = base + tid;
        float x0 = x_raw[2*idx], x1 = x_raw[2*idx+1];
        out_raw[idx] = backbone(x0, x1) + qhead(x0, x1);
    }
}

extern "C" void kernel_launch(void* const* d_in, const int* in_sizes, int n_in,
                              void* d_out, int out_size) {
    const float* x      = (const float*)d_in[0];  // [N,2]
    const float* Ws     = (const float*)d_in[1];  // [5,2,2]
    const float* bs     = (const float*)d_in[2];  // [5,2]
    const float* scales = (const float*)d_in[3];  // [5,2]
    const float* shifts = (const float*)d_in[4];  // [5,2]
    const float* Wf     = (const float*)d_in[5];  // [1,2]
    const float* bf     = (const float*)d_in[6];  // [1]
    const float* theta  = (const float*)d_in[7];  // [2,2]

    const int n = out_size;
    const int noct = n >> 3;              // 8 elements per thread, one pass

    const int threads = 256;
    int blocks = (noct + threads - 1) / threads;   // exact: 2048 at N=4M
    if (blocks < 1) blocks = 1;

    fraud_hybrid_fused<<<blocks, threads>>>(
        (const float4*)x, (float4*)d_out, x, (float*)d_out,
        Ws, bs, scales, shifts, Wf, bf, theta, n, noct);
}